// round 11
// baseline (speedup 1.0000x reference)
#include <cuda_runtime.h>
#include <cuda_fp16.h>

#define NX 192
#define NY 192
#define NZ 192
#define NB 2
#define WIN 9
#define PAD 4
#define WS_INV (1.0f / 729.0f)
#define EPS 1e-5f

#define YC 48                   /* y-chunk per (blockIdx half, threadIdx.y) */
#define XCHUNKS 6
#define XC (NX / XCHUNKS)       /* 32 */
#define NZ2 (NZ / 2)            /* 96 float2/half2 per row */

constexpr size_t NTOT  = (size_t)NB * NX * NY * NZ;   // 14,155,776
constexpr size_t NTOT4 = NTOT / 4;                    // uint2 (4 halfs) per channel
constexpr int QUAD_PLANE = NY * NZ / 4;               // uint2 per x-slice = 9216

// Scratch: 5 channels {I_sum, J_sum, I2_sum, J2_sum, IJ_sum}, Z+Y filtered, fp16.
__device__ __half  g_buf[5 * NTOT];
__device__ double  g_accum;

// Persistent-state management: dedicated kernels (proven; fused variants failed).
__global__ void zero_accum_kernel() { g_accum = 0.0; }
__global__ void finalize_kernel(float* __restrict__ out) {
    out[0] = (float)(-g_accum / (double)NTOT);
}
// No-op launches to steer ncu (it profiles the 4th launch) onto pass12.
__global__ void dummy_kernel() {}

__device__ __forceinline__ unsigned int pack_h2(float a, float b) {
    const __half2 h = __floats2half2_rn(a, b);
    return *reinterpret_cast<const unsigned int*>(&h);
}
__device__ __forceinline__ float2 unpack_h2(unsigned int w) {
    return __half22float2(*reinterpret_cast<const __half2*>(&w));
}

// ---------------------------------------------------------------------------
// pass12: fused Z-filter + Y-filter. Thread = float2 z-pair; threadIdx.y = y
// sub-chunk; grid 768 blocks. Depth-2 prefetch pipeline. Ping-pong row
// buffers -> ONE barrier per y-row (a thread can never be 2 barriers ahead,
// and iter y+1 writes the opposite parity buffer). Ring packed uint4+uint.
// ---------------------------------------------------------------------------
__global__ __launch_bounds__(192) void pass12(const float* __restrict__ I,
                                              const float* __restrict__ J) {
    __shared__ float2 sIf[2][2][NZ2 + PAD];        // [chunk][parity][z]
    __shared__ float2 sJf[2][2][NZ2 + PAD];
    __shared__ uint4  ringA[2][9][NZ2];            // q0..q3 packed (A,B) half2
    __shared__ unsigned int ringB[2][9][NZ2];      // q4 packed

    const int c    = threadIdx.y;                  // sub-chunk 0/1
    const int tz   = threadIdx.x;                  // 0..95
    const int id   = blockIdx.x;                   // 0 .. NB*NX*2-1
    const int half = id & 1;
    const int bx   = id >> 1;                      // (b,x): 0..NB*NX-1
    const size_t planeBase = (size_t)bx * NY * NZ;
    const int y0 = (half * 2 + c) * YC;
    const int ylEnd = y0 + YC + PAD;

    if (tz < 2) {   // z halo: 2 float2 each side, both parities
#pragma unroll
        for (int pb = 0; pb < 2; ++pb) {
            sIf[c][pb][tz] = make_float2(0.f, 0.f);
            sJf[c][pb][tz] = make_float2(0.f, 0.f);
            sIf[c][pb][NZ2 + 2 + tz] = make_float2(0.f, 0.f);
            sJf[c][pb][NZ2 + 2 + tz] = make_float2(0.f, 0.f);
        }
    }

    const float2* __restrict__ I2 = reinterpret_cast<const float2*>(I + planeBase);
    const float2* __restrict__ J2 = reinterpret_cast<const float2*>(J + planeBase);
    __half2* __restrict__ h2buf = reinterpret_cast<__half2*>(g_buf);

    auto load_row = [&](int row, float2& rI, float2& rJ) {
        if (row >= 0 && row < NY && row < ylEnd) {
            rI = I2[(size_t)row * NZ2 + tz];
            rJ = J2[(size_t)row * NZ2 + tz];
        } else {
            rI = make_float2(0.f, 0.f);
            rJ = make_float2(0.f, 0.f);
        }
    };

    const int yl0 = y0 - PAD;
    float2 aI, aJ, bI, bJ;                 // a = row yl, b = row yl+1
    load_row(yl0,     aI, aJ);
    load_row(yl0 + 1, bI, bJ);

    float sA0 = 0.f, sA1 = 0.f, sA2 = 0.f, sA3 = 0.f, sA4 = 0.f;
    float sB0 = 0.f, sB1 = 0.f, sB2 = 0.f, sB3 = 0.f, sB4 = 0.f;
    int slot = ((yl0 % 9) + 9) % 9;

    for (int yl = yl0; yl < ylEnd; ++yl) {
        const int pb = yl & 1;
        sIf[c][pb][tz + 2] = aI;
        sJf[c][pb][tz + 2] = aJ;
        __syncthreads();                   // single barrier per row

        // Rotate pipeline; issue load for row yl+2 (consumed 2 iters later).
        aI = bI; aJ = bJ;
        load_row(yl + 2, bI, bJ);

        // Window u[0..9] = raw z (2*tz-4 .. 2*tz+5), aligned float2 reads.
        float u[10], v[10];
#pragma unroll
        for (int j = 0; j < 5; ++j) {
            const float2 tu = sIf[c][pb][tz + j];
            const float2 tv = sJf[c][pb][tz + j];
            u[2 * j] = tu.x; u[2 * j + 1] = tu.y;
            v[2 * j] = tv.x; v[2 * j + 1] = tv.y;
        }
        // Shared middle (taps 1..8), then edge taps for the two outputs.
        float m0 = 0.f, m1 = 0.f, m2 = 0.f, m3 = 0.f, m4 = 0.f;
#pragma unroll
        for (int i = 1; i < 9; ++i) {
            m0 += u[i];             m1 += v[i];
            m2 = fmaf(u[i], u[i], m2);
            m3 = fmaf(v[i], v[i], m3);
            m4 = fmaf(u[i], v[i], m4);
        }
        const float qA0 = m0 + u[0],                 qB0 = m0 + u[9];
        const float qA1 = m1 + v[0],                 qB1 = m1 + v[9];
        const float qA2 = fmaf(u[0], u[0], m2),      qB2 = fmaf(u[9], u[9], m2);
        const float qA3 = fmaf(v[0], v[0], m3),      qB3 = fmaf(v[9], v[9], m3);
        const float qA4 = fmaf(u[0], v[0], m4),      qB4 = fmaf(u[9], v[9], m4);

        sA0 += qA0; sA1 += qA1; sA2 += qA2; sA3 += qA3; sA4 += qA4;
        sB0 += qB0; sB1 += qB1; sB2 += qB2; sB3 += qB3; sB4 += qB4;

        {
            uint4 w;
            w.x = pack_h2(qA0, qB0);
            w.y = pack_h2(qA1, qB1);
            w.z = pack_h2(qA2, qB2);
            w.w = pack_h2(qA3, qB3);
            ringA[c][slot][tz] = w;
            ringB[c][slot][tz] = pack_h2(qA4, qB4);
        }

        if (yl >= y0 + PAD) {
            const int yo = yl - PAD;
            const size_t o = planeBase / 2 + (size_t)yo * NZ2 + tz;
            h2buf[0 * (NTOT / 2) + o] = __floats2half2_rn(sA0, sB0);
            h2buf[1 * (NTOT / 2) + o] = __floats2half2_rn(sA1, sB1);
            h2buf[2 * (NTOT / 2) + o] = __floats2half2_rn(sA2, sB2);
            h2buf[3 * (NTOT / 2) + o] = __floats2half2_rn(sA3, sB3);
            h2buf[4 * (NTOT / 2) + o] = __floats2half2_rn(sA4, sB4);
            // Row yl-8 lives in slot (slot+1)%9 (read before next overwrite).
            const int so = (slot + 1 == 9) ? 0 : slot + 1;
            const uint4 w = ringA[c][so][tz];
            const unsigned int w4 = ringB[c][so][tz];
            float2 f;
            f = unpack_h2(w.x); sA0 -= f.x; sB0 -= f.y;
            f = unpack_h2(w.y); sA1 -= f.x; sB1 -= f.y;
            f = unpack_h2(w.z); sA2 -= f.x; sB2 -= f.y;
            f = unpack_h2(w.w); sA3 -= f.x; sB3 -= f.y;
            f = unpack_h2(w4);  sA4 -= f.x; sB4 -= f.y;
        }
        slot = (slot + 1 == 9) ? 0 : slot + 1;
    }
}

// ---------------------------------------------------------------------------
// pass3: sliding 9-slice window along X, fused NCC + mean. Each thread owns
// 4 consecutive z-voxels (uint2 = 2 half2 per channel -> LDG.64).
// X split into XCHUNKS=6 ranges (preamble overhead 25%).
// ---------------------------------------------------------------------------
__global__ __launch_bounds__(256) void pass3_x_ncc() {
    const int x0 = blockIdx.y * XC;
    const int t  = blockIdx.x * blockDim.x + threadIdx.x;  // 0 .. NB*QUAD_PLANE-1
    const int b  = t / QUAD_PLANE;
    const int yz = t % QUAD_PLANE;

    const uint2* __restrict__ pk[5];
    {
        const uint2* base = reinterpret_cast<const uint2*>(g_buf) +
                            (size_t)b * NX * QUAD_PLANE + yz;
#pragma unroll
        for (int k = 0; k < 5; ++k) pk[k] = base + (size_t)k * NTOT4;
    }

    float s[5][4];
#pragma unroll
    for (int k = 0; k < 5; ++k)
#pragma unroll
        for (int l = 0; l < 4; ++l) s[k][l] = 0.f;

    auto slice_add = [&](int xs) {
        const size_t o = (size_t)xs * QUAD_PLANE;
#pragma unroll
        for (int k = 0; k < 5; ++k) {
            const uint2 w = pk[k][o];
            const float2 fl = unpack_h2(w.x);
            const float2 fh = unpack_h2(w.y);
            s[k][0] += fl.x; s[k][1] += fl.y; s[k][2] += fh.x; s[k][3] += fh.y;
        }
    };
    auto slice_sub = [&](int xs) {
        const size_t o = (size_t)xs * QUAD_PLANE;
#pragma unroll
        for (int k = 0; k < 5; ++k) {
            const uint2 w = pk[k][o];
            const float2 fl = unpack_h2(w.x);
            const float2 fh = unpack_h2(w.y);
            s[k][0] -= fl.x; s[k][1] -= fl.y; s[k][2] -= fh.x; s[k][3] -= fh.y;
        }
    };

    const int pre0 = (x0 - PAD > 0) ? (x0 - PAD) : 0;
#pragma unroll 4
    for (int x = pre0; x < x0 + PAD; ++x) slice_add(x);

    float acc = 0.f;
#pragma unroll 2
    for (int x = x0; x < x0 + XC; ++x) {
        const int xp = x + PAD;
        if (xp < NX) slice_add(xp);
#pragma unroll
        for (int l = 0; l < 4; ++l) {
            const float cross = s[4][l] - s[0][l] * s[1][l] * WS_INV;
            const float ivar  = s[2][l] - s[0][l] * s[0][l] * WS_INV;
            const float jvar  = s[3][l] - s[1][l] * s[1][l] * WS_INV;
            acc += (cross * cross) / (ivar * jvar + EPS);
        }
        const int xm = x - PAD;
        if (xm >= 0) slice_sub(xm);
    }

    __shared__ float red[256];
    red[threadIdx.x] = acc;
    __syncthreads();
#pragma unroll
    for (int o = 128; o > 0; o >>= 1) {
        if (threadIdx.x < o) red[threadIdx.x] += red[threadIdx.x + o];
        __syncthreads();
    }
    if (threadIdx.x == 0) atomicAdd(&g_accum, (double)red[0]);
}

extern "C" void kernel_launch(void* const* d_in, const int* in_sizes, int n_in,
                              void* d_out, int out_size) {
    const float* I = (const float*)d_in[0];
    const float* J = (const float*)d_in[1];
    float* out = (float*)d_out;

    zero_accum_kernel<<<1, 1>>>();
    dummy_kernel<<<1, 1>>>();   // steer ncu: profiled launch is the 4th
    dummy_kernel<<<1, 1>>>();   // -> lands on pass12 below
    pass12<<<NB * NX * 2, dim3(NZ2, 2)>>>(I, J);
    {
        dim3 grid((NB * QUAD_PLANE) / 256, XCHUNKS);
        pass3_x_ncc<<<grid, 256>>>();
    }
    finalize_kernel<<<1, 1>>>(out);
}

// round 12
// speedup vs baseline: 1.1910x; 1.1910x over previous
#include <cuda_runtime.h>
#include <cuda_fp16.h>

#define NX 192
#define NY 192
#define NZ 192
#define NB 2
#define WIN 9
#define PAD 4
#define WS_INV (1.0f / 729.0f)
#define EPS 1e-5f

#define YC 48                   /* y-chunk per (blockIdx half, threadIdx.y) */
#define XCHUNKS 6
#define XC (NX / XCHUNKS)       /* 32 */
#define NZ2 (NZ / 2)            /* 96 float2/half2 per row */

constexpr size_t NTOT  = (size_t)NB * NX * NY * NZ;   // 14,155,776
constexpr size_t NTOT4 = NTOT / 4;                    // uint2 (4 halfs) per channel
constexpr int QUAD_PLANE = NY * NZ / 4;               // uint2 per x-slice = 9216

// Scratch: 5 channels {I_sum, J_sum, I2_sum, J2_sum, IJ_sum}, Z+Y filtered, fp16.
__device__ __half  g_buf[5 * NTOT];
__device__ double  g_accum;

// Persistent-state management: dedicated kernels (proven; fused variants failed).
__global__ void zero_accum_kernel() { g_accum = 0.0; }
__global__ void finalize_kernel(float* __restrict__ out) {
    out[0] = (float)(-g_accum / (double)NTOT);
}

__device__ __forceinline__ unsigned int pack_h2(float a, float b) {
    const __half2 h = __floats2half2_rn(a, b);
    return *reinterpret_cast<const unsigned int*>(&h);
}
__device__ __forceinline__ float2 unpack_h2(unsigned int w) {
    return __half22float2(*reinterpret_cast<const __half2*>(&w));
}

// ---------------------------------------------------------------------------
// pass12: fused Z-filter + Y-filter. Thread = float2 z-pair; threadIdx.y = y
// sub-chunk; grid 768 blocks. Single-buffer staging with two barriers/row
// (proven R8/R10 form). Depth-2 prefetch. 8-slot ring (window 9 needs only 8
// history rows; current row's q is in regs when old rows are read): smem
// 33.9KB. __launch_bounds__(192,6) forces <=56 regs -> 6 blocks/SM (36 warps;
// R11 profile showed 62 regs capped us at 5 blocks / 40% occ, latency-bound).
// ---------------------------------------------------------------------------
__global__ __launch_bounds__(192, 6) void pass12(const float* __restrict__ I,
                                                 const float* __restrict__ J) {
    __shared__ float2 sIf[2][NZ2 + PAD];           // 100 float2 per chunk
    __shared__ float2 sJf[2][NZ2 + PAD];
    __shared__ uint4  ringA[2][8][NZ2];            // q0..q3 packed (A,B) half2
    __shared__ unsigned int ringB[2][8][NZ2];      // q4 packed

    const int c    = threadIdx.y;                  // sub-chunk 0/1
    const int tz   = threadIdx.x;                  // 0..95
    const int id   = blockIdx.x;                   // 0 .. NB*NX*2-1
    const int half = id & 1;
    const int bx   = id >> 1;                      // (b,x): 0..NB*NX-1
    const size_t planeBase = (size_t)bx * NY * NZ;
    const int y0 = (half * 2 + c) * YC;
    const int ylEnd = y0 + YC + PAD;

    if (tz < 2) {   // z halo: 2 float2 each side
        sIf[c][tz] = make_float2(0.f, 0.f);
        sJf[c][tz] = make_float2(0.f, 0.f);
        sIf[c][NZ2 + 2 + tz] = make_float2(0.f, 0.f);
        sJf[c][NZ2 + 2 + tz] = make_float2(0.f, 0.f);
    }

    const float2* __restrict__ I2 = reinterpret_cast<const float2*>(I + planeBase);
    const float2* __restrict__ J2 = reinterpret_cast<const float2*>(J + planeBase);
    __half2* __restrict__ h2buf = reinterpret_cast<__half2*>(g_buf);

    auto load_row = [&](int row, float2& rI, float2& rJ) {
        if (row >= 0 && row < NY && row < ylEnd) {
            rI = I2[(size_t)row * NZ2 + tz];
            rJ = J2[(size_t)row * NZ2 + tz];
        } else {
            rI = make_float2(0.f, 0.f);
            rJ = make_float2(0.f, 0.f);
        }
    };

    const int yl0 = y0 - PAD;
    float2 aI, aJ, bI, bJ;                 // a = row yl, b = row yl+1
    load_row(yl0,     aI, aJ);
    load_row(yl0 + 1, bI, bJ);

    float sA0 = 0.f, sA1 = 0.f, sA2 = 0.f, sA3 = 0.f, sA4 = 0.f;
    float sB0 = 0.f, sB1 = 0.f, sB2 = 0.f, sB3 = 0.f, sB4 = 0.f;

    for (int yl = yl0; yl < ylEnd; ++yl) {
        __syncthreads();                   // prior row's taps consumed
        sIf[c][tz + 2] = aI;
        sJf[c][tz + 2] = aJ;
        __syncthreads();

        // Rotate pipeline; issue load for row yl+2 (consumed 2 iters later).
        aI = bI; aJ = bJ;
        load_row(yl + 2, bI, bJ);

        // Window u[0..9] = raw z (2*tz-4 .. 2*tz+5), aligned float2 reads.
        float u[10], v[10];
#pragma unroll
        for (int j = 0; j < 5; ++j) {
            const float2 tu = sIf[c][tz + j];
            const float2 tv = sJf[c][tz + j];
            u[2 * j] = tu.x; u[2 * j + 1] = tu.y;
            v[2 * j] = tv.x; v[2 * j + 1] = tv.y;
        }
        // Shared middle (taps 1..8), then edge taps for the two outputs.
        float m0 = 0.f, m1 = 0.f, m2 = 0.f, m3 = 0.f, m4 = 0.f;
#pragma unroll
        for (int i = 1; i < 9; ++i) {
            m0 += u[i];             m1 += v[i];
            m2 = fmaf(u[i], u[i], m2);
            m3 = fmaf(v[i], v[i], m3);
            m4 = fmaf(u[i], v[i], m4);
        }
        const float qA0 = m0 + u[0],                 qB0 = m0 + u[9];
        const float qA1 = m1 + v[0],                 qB1 = m1 + v[9];
        const float qA2 = fmaf(u[0], u[0], m2),      qB2 = fmaf(u[9], u[9], m2);
        const float qA3 = fmaf(v[0], v[0], m3),      qB3 = fmaf(v[9], v[9], m3);
        const float qA4 = fmaf(u[0], v[0], m4),      qB4 = fmaf(u[9], v[9], m4);

        sA0 += qA0; sA1 += qA1; sA2 += qA2; sA3 += qA3; sA4 += qA4;
        sB0 += qB0; sB1 += qB1; sB2 += qB2; sB3 += qB3; sB4 += qB4;

        const int slot = yl & 7;           // 8-slot ring; AND safe for yl<0

        if (yl >= y0 + PAD) {
            const int yo = yl - PAD;
            const size_t o = planeBase / 2 + (size_t)yo * NZ2 + tz;
            h2buf[0 * (NTOT / 2) + o] = __floats2half2_rn(sA0, sB0);
            h2buf[1 * (NTOT / 2) + o] = __floats2half2_rn(sA1, sB1);
            h2buf[2 * (NTOT / 2) + o] = __floats2half2_rn(sA2, sB2);
            h2buf[3 * (NTOT / 2) + o] = __floats2half2_rn(sA3, sB3);
            h2buf[4 * (NTOT / 2) + o] = __floats2half2_rn(sA4, sB4);
            // Row yl-8 lives in slot (yl-8)&7 == yl&7: read it, then the
            // write below replaces it with the current row q_yl.
            const uint4 w = ringA[c][slot][tz];
            const unsigned int w4 = ringB[c][slot][tz];
            float2 f;
            f = unpack_h2(w.x); sA0 -= f.x; sB0 -= f.y;
            f = unpack_h2(w.y); sA1 -= f.x; sB1 -= f.y;
            f = unpack_h2(w.z); sA2 -= f.x; sB2 -= f.y;
            f = unpack_h2(w.w); sA3 -= f.x; sB3 -= f.y;
            f = unpack_h2(w4);  sA4 -= f.x; sB4 -= f.y;
        }

        {
            uint4 w;
            w.x = pack_h2(qA0, qB0);
            w.y = pack_h2(qA1, qB1);
            w.z = pack_h2(qA2, qB2);
            w.w = pack_h2(qA3, qB3);
            ringA[c][slot][tz] = w;
            ringB[c][slot][tz] = pack_h2(qA4, qB4);
        }
    }
}

// ---------------------------------------------------------------------------
// pass3: sliding 9-slice window along X, fused NCC + mean. Each thread owns
// 4 consecutive z-voxels (uint2 = 2 half2 per channel -> LDG.64).
// X split into XCHUNKS=6 ranges (preamble overhead 25%).
// ---------------------------------------------------------------------------
__global__ __launch_bounds__(256) void pass3_x_ncc() {
    const int x0 = blockIdx.y * XC;
    const int t  = blockIdx.x * blockDim.x + threadIdx.x;  // 0 .. NB*QUAD_PLANE-1
    const int b  = t / QUAD_PLANE;
    const int yz = t % QUAD_PLANE;

    const uint2* __restrict__ pk[5];
    {
        const uint2* base = reinterpret_cast<const uint2*>(g_buf) +
                            (size_t)b * NX * QUAD_PLANE + yz;
#pragma unroll
        for (int k = 0; k < 5; ++k) pk[k] = base + (size_t)k * NTOT4;
    }

    float s[5][4];
#pragma unroll
    for (int k = 0; k < 5; ++k)
#pragma unroll
        for (int l = 0; l < 4; ++l) s[k][l] = 0.f;

    auto slice_add = [&](int xs) {
        const size_t o = (size_t)xs * QUAD_PLANE;
#pragma unroll
        for (int k = 0; k < 5; ++k) {
            const uint2 w = pk[k][o];
            const float2 fl = unpack_h2(w.x);
            const float2 fh = unpack_h2(w.y);
            s[k][0] += fl.x; s[k][1] += fl.y; s[k][2] += fh.x; s[k][3] += fh.y;
        }
    };
    auto slice_sub = [&](int xs) {
        const size_t o = (size_t)xs * QUAD_PLANE;
#pragma unroll
        for (int k = 0; k < 5; ++k) {
            const uint2 w = pk[k][o];
            const float2 fl = unpack_h2(w.x);
            const float2 fh = unpack_h2(w.y);
            s[k][0] -= fl.x; s[k][1] -= fl.y; s[k][2] -= fh.x; s[k][3] -= fh.y;
        }
    };

    const int pre0 = (x0 - PAD > 0) ? (x0 - PAD) : 0;
#pragma unroll 4
    for (int x = pre0; x < x0 + PAD; ++x) slice_add(x);

    float acc = 0.f;
#pragma unroll 2
    for (int x = x0; x < x0 + XC; ++x) {
        const int xp = x + PAD;
        if (xp < NX) slice_add(xp);
#pragma unroll
        for (int l = 0; l < 4; ++l) {
            const float cross = s[4][l] - s[0][l] * s[1][l] * WS_INV;
            const float ivar  = s[2][l] - s[0][l] * s[0][l] * WS_INV;
            const float jvar  = s[3][l] - s[1][l] * s[1][l] * WS_INV;
            acc += (cross * cross) / (ivar * jvar + EPS);
        }
        const int xm = x - PAD;
        if (xm >= 0) slice_sub(xm);
    }

    __shared__ float red[256];
    red[threadIdx.x] = acc;
    __syncthreads();
#pragma unroll
    for (int o = 128; o > 0; o >>= 1) {
        if (threadIdx.x < o) red[threadIdx.x] += red[threadIdx.x + o];
        __syncthreads();
    }
    if (threadIdx.x == 0) atomicAdd(&g_accum, (double)red[0]);
}

extern "C" void kernel_launch(void* const* d_in, const int* in_sizes, int n_in,
                              void* d_out, int out_size) {
    const float* I = (const float*)d_in[0];
    const float* J = (const float*)d_in[1];
    float* out = (float*)d_out;

    zero_accum_kernel<<<1, 1>>>();
    pass12<<<NB * NX * 2, dim3(NZ2, 2)>>>(I, J);
    {
        dim3 grid((NB * QUAD_PLANE) / 256, XCHUNKS);
        pass3_x_ncc<<<grid, 256>>>();
    }
    finalize_kernel<<<1, 1>>>(out);
}